// round 15
// baseline (speedup 1.0000x reference)
#include <cuda_runtime.h>
#include <cuda_fp16.h>
#include <math.h>

#define H 256
#define NB_CLASSES 7
#define B_MAX 14000
#define N_MAX 100000
#define EPS 1e-8f
#define NREP 16

// Scratch (allocation-free rule: __device__ globals)
__device__ __align__(16) __half g_eh[(size_t)N_MAX * H];  // fp16 embeds (51.2 MB)
__device__ float g_n1[N_MAX];                             // ||e * w_nb||^2
__device__ float g_n2[N_MAX];                             // ||e * w_nb2||^2
__device__ __align__(16) __half g_rr[(size_t)B_MAX * H];  // rawret fp16 (7.2 MB)
__device__ __align__(8) float g_csum_r[NREP][NB_CLASSES * H];  // replicated sums
__device__ float g_ccnt_r[NREP][NB_CLASSES];
__device__ __align__(16) __half g_avh[NB_CLASSES * H];    // (ave/an) fp16

__device__ __forceinline__ float wred_sum(float v) {
    #pragma unroll
    for (int o = 16; o; o >>= 1) v += __shfl_xor_sync(0xFFFFFFFFu, v, o);
    return v;
}

// ---------------------------------------------------------------------------
// Kernel C: fp32 -> fp16 table + per-row weighted norms. Warp per 4 rows
// (MLP 8). Blocks 0..15 zero their replica accumulator.
// ---------------------------------------------------------------------------
__global__ void kc(const float* __restrict__ embeds,
                   const float* __restrict__ wnb,
                   const float* __restrict__ wnb2,
                   int N) {
    if (blockIdx.x < NREP) {
        float* cs = g_csum_r[blockIdx.x];
        for (int j = threadIdx.x; j < NB_CLASSES * H; j += blockDim.x) cs[j] = 0.f;
        if (threadIdx.x < NB_CLASSES) g_ccnt_r[blockIdx.x][threadIdx.x] = 0.f;
    }
    const int lane = threadIdx.x & 31;
    const int gw = (blockIdx.x * blockDim.x + threadIdx.x) >> 5;
    const int nw = (gridDim.x * blockDim.x) >> 5;

    const float4 wa0 = ((const float4*)wnb)[2 * lane];
    const float4 wa1 = ((const float4*)wnb)[2 * lane + 1];
    const float4 wb0 = ((const float4*)wnb2)[2 * lane];
    const float4 wb1 = ((const float4*)wnb2)[2 * lane + 1];
    float wav[8] = {wa0.x, wa0.y, wa0.z, wa0.w, wa1.x, wa1.y, wa1.z, wa1.w};
    float wbv[8] = {wb0.x, wb0.y, wb0.z, wb0.w, wb1.x, wb1.y, wb1.z, wb1.w};

    for (int r0 = gw; r0 < N; r0 += 4 * nw) {
        int rr[4];
        float4 A[4], Bv[4];
        #pragma unroll
        for (int q = 0; q < 4; q++) {
            rr[q] = r0 + q * nw;
            if (rr[q] < N) {
                const float4* s = (const float4*)(embeds + (size_t)rr[q] * H);
                A[q]  = s[2 * lane];
                Bv[q] = s[2 * lane + 1];
            }
        }

        float n1[4] = {0, 0, 0, 0}, n2[4] = {0, 0, 0, 0};
        #pragma unroll
        for (int q = 0; q < 4; q++) {
            if (rr[q] < N) {
                const float e[8] = {A[q].x, A[q].y, A[q].z, A[q].w,
                                    Bv[q].x, Bv[q].y, Bv[q].z, Bv[q].w};
                #pragma unroll
                for (int i = 0; i < 8; i++) {
                    const float x1 = e[i] * wav[i];
                    const float x2 = e[i] * wbv[i];
                    n1[q] = fmaf(x1, x1, n1[q]);
                    n2[q] = fmaf(x2, x2, n2[q]);
                }
                union { uint4 u; __half2 h[4]; } pk;
                #pragma unroll
                for (int i = 0; i < 4; i++)
                    pk.h[i] = __float22half2_rn(make_float2(e[2 * i], e[2 * i + 1]));
                ((uint4*)(g_eh + (size_t)rr[q] * H))[lane] = pk.u;
            }
        }

        // interleaved butterflies over 8 independent values
        #pragma unroll
        for (int o = 16; o; o >>= 1) {
            #pragma unroll
            for (int q = 0; q < 4; q++) {
                n1[q] += __shfl_xor_sync(0xFFFFFFFFu, n1[q], o);
                n2[q] += __shfl_xor_sync(0xFFFFFFFFu, n2[q], o);
            }
        }
        if (lane == 0) {
            #pragma unroll
            for (int q = 0; q < 4; q++)
                if (rr[q] < N) { g_n1[rr[q]] = n1[q]; g_n2[rr[q]] = n2[q]; }
        }
    }
}

// ---------------------------------------------------------------------------
// Kernel 1 (K1=16, K2=32): 1 CTA per row b, 128 threads (4 warps), occ 8.
// R13 structure (single __syncthreads; replicated class atomics).
// wsum weights read as float4 broadcast chunks (1 wavefront per 4 rows).
// ---------------------------------------------------------------------------
template<int K1, int K2>
__global__ void __launch_bounds__(128, 8)
k1s(const float* __restrict__ wself,
    const float* __restrict__ wnb,
    const float* __restrict__ wnb2,
    const int* __restrict__ idx,
    const int* __restrict__ labels,
    const int* __restrict__ nbr,
    const int* __restrict__ nbr2) {
    constexpr int KT = K1 + K2;   // 48
    constexpr int JP = KT / 4;    // 12 rows per warp
    constexpr int J1 = K1 / 4;    // 4: first J1 j's are 1-hop

    __shared__ __align__(16) __half nb_h[KT * H];  // raw fp16 rows (24.6 KB)
    __shared__ float nrm_s[KT];
    __shared__ float dots[KT];
    __shared__ __align__(16) float wgt[4][KT];     // per-warp softmax weights

    const int b    = blockIdx.x;
    const int tid  = threadIdx.x;
    const int lane = tid & 31;
    const int warp = tid >> 5;

    int rows[JP];
    #pragma unroll
    for (int j = 0; j < JP; j++) {
        const int k = warp + 4 * j;
        rows[j] = (j < J1) ? __ldg(&nbr[b * K1 + k]) : __ldg(&nbr2[b * K2 + k - K1]);
    }
    #pragma unroll
    for (int j = 0; j < JP; j++) {
        const int k = warp + 4 * j;
        const __half* gp = g_eh + (size_t)rows[j] * H + lane * 8;
        const unsigned sp = (unsigned)__cvta_generic_to_shared(nb_h + k * H + lane * 8);
        asm volatile("cp.async.cg.shared.global [%0], [%1], 16;\n"
                     :: "r"(sp), "l"(gp) : "memory");
    }
    asm volatile("cp.async.commit_group;\n" ::: "memory");

    if (tid < KT) {
        const int r = (tid < K1) ? nbr[b * K1 + tid] : nbr2[b * K2 + tid - K1];
        nrm_s[tid] = (tid < K1) ? g_n1[r] : g_n2[r];
    }

    const int crow = idx[b];
    const int lbl  = labels[b];

    float c1v[8], c2v[8];
    float cn;
    {
        union { uint4 u; __half2 h[4]; } cr;
        cr.u = ((const uint4*)(g_eh + (size_t)crow * H))[lane];
        const float4 ws0 = ((const float4*)wself)[2 * lane];
        const float4 ws1 = ((const float4*)wself)[2 * lane + 1];
        const float wsv[8] = {ws0.x, ws0.y, ws0.z, ws0.w, ws1.x, ws1.y, ws1.z, ws1.w};
        const float2 e0 = __half22float2(cr.h[0]);
        const float2 e1 = __half22float2(cr.h[1]);
        const float2 e2 = __half22float2(cr.h[2]);
        const float2 e3 = __half22float2(cr.h[3]);
        const float ce[8] = {e0.x, e0.y, e1.x, e1.y, e2.x, e2.y, e3.x, e3.y};

        float cvs[8];
        float cs = 0.f;
        #pragma unroll
        for (int i = 0; i < 8; i++) {
            cvs[i] = ce[i] * wsv[i];
            cs = fmaf(cvs[i], cvs[i], cs);
        }
        cn = fmaxf(sqrtf(wred_sum(cs)), EPS);

        const float4 wa0 = ((const float4*)wnb)[2 * lane];
        const float4 wa1 = ((const float4*)wnb)[2 * lane + 1];
        const float4 wb0 = ((const float4*)wnb2)[2 * lane];
        const float4 wb1 = ((const float4*)wnb2)[2 * lane + 1];
        const float wav[8] = {wa0.x, wa0.y, wa0.z, wa0.w, wa1.x, wa1.y, wa1.z, wa1.w};
        const float wbv[8] = {wb0.x, wb0.y, wb0.z, wb0.w, wb1.x, wb1.y, wb1.z, wb1.w};
        #pragma unroll
        for (int i = 0; i < 8; i++) {
            c1v[i] = cvs[i] * wav[i];
            c2v[i] = cvs[i] * wbv[i];
        }
    }

    const float2 ws2 = ((const float2*)wself)[tid];
    const float2 ev2 = __half22float2(((const __half2*)(g_eh + (size_t)crow * H))[tid]);
    const float2 cv = make_float2(ev2.x * ws2.x, ev2.y * ws2.y);

    asm volatile("cp.async.wait_group 0;\n" ::: "memory");

    float d[JP];
    #pragma unroll
    for (int j = 0; j < JP; j++) {
        const int k = warp + 4 * j;
        union { uint4 u; __half2 h[4]; } pk;
        pk.u = ((const uint4*)(nb_h + k * H))[lane];
        const float* cw = (j < J1) ? c1v : c2v;
        const float2 v0 = __half22float2(pk.h[0]);
        const float2 v1 = __half22float2(pk.h[1]);
        const float2 v2 = __half22float2(pk.h[2]);
        const float2 v3 = __half22float2(pk.h[3]);
        d[j] = v0.x * cw[0] + v0.y * cw[1] + v1.x * cw[2] + v1.y * cw[3]
             + v2.x * cw[4] + v2.y * cw[5] + v3.x * cw[6] + v3.y * cw[7];
    }
    #pragma unroll
    for (int o = 16; o; o >>= 1) {
        #pragma unroll
        for (int j = 0; j < JP; j++)
            d[j] += __shfl_xor_sync(0xFFFFFFFFu, d[j], o);
    }
    if (lane == 0) {
        #pragma unroll
        for (int j = 0; j < JP; j++) dots[warp + 4 * j] = d[j];
    }
    __syncthreads();   // THE barrier

    {
        const int ka = lane, kb = lane + 32;
        const float cosA = dots[ka] / (cn * fmaxf(sqrtf(nrm_s[ka]), EPS));
        const float cosB = (kb < KT)
            ? dots[kb] / (cn * fmaxf(sqrtf(nrm_s[kb]), EPS)) : -1e30f;
        float m = fmaxf(cosA, cosB);
        #pragma unroll
        for (int o = 16; o; o >>= 1) m = fmaxf(m, __shfl_xor_sync(0xFFFFFFFFu, m, o));
        const float eA = __expf(cosA - m);
        const float eB = (kb < KT) ? __expf(cosB - m) : 0.f;
        const float inv = 1.f / wred_sum(eA + eB);
        wgt[warp][ka] = eA * inv;
        if (kb < KT) wgt[warp][kb] = eB * inv;
    }
    __syncwarp();

    // --- weighted sum: float4 weight chunks (1 broadcast wf per 4 rows) ---
    const float* wg = wgt[warp];
    float ax = 0.f, ay = 0.f, bx = 0.f, by = 0.f;
    #pragma unroll
    for (int k4 = 0; k4 < K1; k4 += 4) {
        const float4 wq = *((const float4*)(wg + k4));
        const float2 va = __half22float2(((const __half2*)(nb_h + (k4 + 0) * H))[tid]);
        const float2 vb = __half22float2(((const __half2*)(nb_h + (k4 + 1) * H))[tid]);
        const float2 vc = __half22float2(((const __half2*)(nb_h + (k4 + 2) * H))[tid]);
        const float2 vd = __half22float2(((const __half2*)(nb_h + (k4 + 3) * H))[tid]);
        ax = fmaf(wq.x, va.x, ax); ay = fmaf(wq.x, va.y, ay);
        ax = fmaf(wq.y, vb.x, ax); ay = fmaf(wq.y, vb.y, ay);
        ax = fmaf(wq.z, vc.x, ax); ay = fmaf(wq.z, vc.y, ay);
        ax = fmaf(wq.w, vd.x, ax); ay = fmaf(wq.w, vd.y, ay);
    }
    #pragma unroll
    for (int k4 = K1; k4 < KT; k4 += 4) {
        const float4 wq = *((const float4*)(wg + k4));
        const float2 va = __half22float2(((const __half2*)(nb_h + (k4 + 0) * H))[tid]);
        const float2 vb = __half22float2(((const __half2*)(nb_h + (k4 + 1) * H))[tid]);
        const float2 vc = __half22float2(((const __half2*)(nb_h + (k4 + 2) * H))[tid]);
        const float2 vd = __half22float2(((const __half2*)(nb_h + (k4 + 3) * H))[tid]);
        bx = fmaf(wq.x, va.x, bx); by = fmaf(wq.x, va.y, by);
        bx = fmaf(wq.y, vb.x, bx); by = fmaf(wq.y, vb.y, by);
        bx = fmaf(wq.z, vc.x, bx); by = fmaf(wq.z, vc.y, by);
        bx = fmaf(wq.w, vd.x, bx); by = fmaf(wq.w, vd.y, by);
    }
    const float2 wa = ((const float2*)wnb)[tid];
    const float2 wb = ((const float2*)wnb2)[tid];
    const float rx = ax * wa.x + bx * wb.x + cv.x;
    const float ry = ay * wa.y + by * wb.y + cv.y;

    ((__half2*)g_rr)[(size_t)b * (H / 2) + tid] =
        __float22half2_rn(make_float2(rx, ry));

    float* csr = g_csum_r[b & (NREP - 1)];
    atomicAdd((float2*)&csr[lbl * H + 2 * tid], make_float2(rx, ry));
    if (tid == 0) atomicAdd(&g_ccnt_r[b & (NREP - 1)][lbl], 1.f);
}

// ---------------------------------------------------------------------------
// Kernel 2r: fold replicas -> per-class mean -> norm -> g_avh = fp16(ave/an).
// ---------------------------------------------------------------------------
__global__ void k2r() {
    __shared__ float red[8];
    const int cc   = blockIdx.x;
    const int t    = threadIdx.x;
    const int lane = t & 31;
    const int warp = t >> 5;

    float s = 0.f;
    #pragma unroll
    for (int r = 0; r < NREP; r++) s += g_csum_r[r][cc * H + t];
    float cnt = 0.f;
    #pragma unroll
    for (int r = 0; r < NREP; r++) cnt += g_ccnt_r[r][cc];
    const float mean = s / fmaxf(cnt, 1.f);

    float sq = wred_sum(mean * mean);
    if (lane == 0) red[warp] = sq;
    __syncthreads();
    float an = 0.f;
    #pragma unroll
    for (int i = 0; i < 8; i++) an += red[i];
    an = fmaxf(sqrtf(an), EPS);

    g_avh[cc * H + t] = __float2half(mean / an);
}

// ---------------------------------------------------------------------------
// Kernel 3: output. 1750 CTAs x 256 threads; ONE WARP PER ROW.
// ---------------------------------------------------------------------------
__global__ void __launch_bounds__(256)
k3(float* __restrict__ out, int B) {
    __shared__ __align__(16) __half avh_s[NB_CLASSES * H];
    const int tid  = threadIdx.x;
    const int lane = tid & 31;
    const int warp = tid >> 5;

    for (int i = tid; i < NB_CLASSES * H / 8; i += 256)
        ((uint4*)avh_s)[i] = ((const uint4*)g_avh)[i];
    __syncthreads();

    const int b = blockIdx.x * 8 + warp;
    if (b >= B) return;

    union { uint4 u; __half2 h[4]; } pk;
    pk.u = ((const uint4*)(g_rr + (size_t)b * H))[lane];
    const float2 v0 = __half22float2(pk.h[0]);
    const float2 v1 = __half22float2(pk.h[1]);
    const float2 v2 = __half22float2(pk.h[2]);
    const float2 v3 = __half22float2(pk.h[3]);

    float d[NB_CLASSES];
    #pragma unroll
    for (int cc = 0; cc < NB_CLASSES; cc++) {
        union { uint4 u; __half2 h[4]; } av;
        av.u = ((const uint4*)(avh_s + cc * H))[lane];
        const float2 a0 = __half22float2(av.h[0]);
        const float2 a1 = __half22float2(av.h[1]);
        const float2 a2 = __half22float2(av.h[2]);
        const float2 a3 = __half22float2(av.h[3]);
        d[cc] = v0.x * a0.x + v0.y * a0.y + v1.x * a1.x + v1.y * a1.y
              + v2.x * a2.x + v2.y * a2.y + v3.x * a3.x + v3.y * a3.y;
    }
    float rsq = v0.x * v0.x + v0.y * v0.y + v1.x * v1.x + v1.y * v1.y
              + v2.x * v2.x + v2.y * v2.y + v3.x * v3.x + v3.y * v3.y;

    #pragma unroll
    for (int o = 16; o; o >>= 1) {
        #pragma unroll
        for (int cc = 0; cc < NB_CLASSES; cc++)
            d[cc] += __shfl_xor_sync(0xFFFFFFFFu, d[cc], o);
        rsq += __shfl_xor_sync(0xFFFFFFFFu, rsq, o);
    }
    const float inv_rbn = 1.f / fmaxf(sqrtf(rsq), EPS);

    float m = -1e30f;
    #pragma unroll
    for (int cc = 0; cc < NB_CLASSES; cc++) {
        d[cc] *= inv_rbn;
        m = fmaxf(m, d[cc]);
    }
    float s = 0.f;
    #pragma unroll
    for (int cc = 0; cc < NB_CLASSES; cc++) {
        d[cc] = __expf(d[cc] - m);
        s += d[cc];
    }
    const float inv = 1.f / s;
    if (lane < NB_CLASSES) {
        float v = 0.f;
        #pragma unroll
        for (int cc = 0; cc < NB_CLASSES; cc++)
            if (lane == cc) v = d[cc] * inv;
        out[b * NB_CLASSES + lane] = v;
    }
}

// ---------------------------------------------------------------------------
// Generic fallback (any K1/K2), fp32 path -> replica 0
// ---------------------------------------------------------------------------
__global__ void kzf() {
    const int i = blockIdx.x * blockDim.x + threadIdx.x;
    if (i < NB_CLASSES * H) {
        #pragma unroll
        for (int r = 0; r < NREP; r++) g_csum_r[r][i] = 0.f;
    }
    if (i < NB_CLASSES) {
        #pragma unroll
        for (int r = 0; r < NREP; r++) g_ccnt_r[r][i] = 0.f;
    }
}

__global__ void k1g(const float* __restrict__ embeds,
                    const float* __restrict__ wself,
                    const float* __restrict__ wnb,
                    const float* __restrict__ wnb2,
                    const int* __restrict__ idx,
                    const int* __restrict__ labels,
                    const int* __restrict__ nbr,
                    const int* __restrict__ nbr2,
                    int K1, int K2) {
    extern __shared__ float sh[];
    const int KT = K1 + K2;
    float* nb_s = sh;
    float* cen  = sh + KT * H;
    float* dots = cen + H;
    float* nrms = dots + KT;
    float* wgt  = nrms + KT;
    float* red  = wgt + KT;

    const int b    = blockIdx.x;
    const int tid  = threadIdx.x;
    const int lane = tid & 31;
    const int warp = tid >> 5;

    const int crow = idx[b];
    const float c = embeds[(size_t)crow * H + tid] * wself[tid];
    cen[tid] = c;
    float cs = wred_sum(c * c);
    if (lane == 0) red[warp] = cs;
    __syncthreads();

    float cn = 0.f;
    #pragma unroll
    for (int i = 0; i < 8; i++) cn += red[i];
    cn = fmaxf(sqrtf(cn), EPS);

    const float4* cen4 = (const float4*)cen;
    const float4 c0 = cen4[lane];
    const float4 c1 = cen4[lane + 32];

    for (int k = warp; k < KT; k += 8) {
        const int r = (k < K1) ? nbr[b * K1 + k] : nbr2[b * K2 + (k - K1)];
        const float4* src = (const float4*)(embeds + (size_t)r * H);
        const float4* wv  = (const float4*)((k < K1) ? wnb : wnb2);
        float4 e0 = src[lane];
        float4 e1 = src[lane + 32];
        const float4 w0 = wv[lane];
        const float4 w1 = wv[lane + 32];
        e0.x *= w0.x; e0.y *= w0.y; e0.z *= w0.z; e0.w *= w0.w;
        e1.x *= w1.x; e1.y *= w1.y; e1.z *= w1.z; e1.w *= w1.w;

        float d = e0.x * c0.x + e0.y * c0.y + e0.z * c0.z + e0.w * c0.w
                + e1.x * c1.x + e1.y * c1.y + e1.z * c1.z + e1.w * c1.w;
        float s = e0.x * e0.x + e0.y * e0.y + e0.z * e0.z + e0.w * e0.w
                + e1.x * e1.x + e1.y * e1.y + e1.z * e1.z + e1.w * e1.w;

        float4* dst = (float4*)(nb_s + k * H);
        dst[lane]      = e0;
        dst[lane + 32] = e1;

        d = wred_sum(d);
        s = wred_sum(s);
        if (lane == 0) { dots[k] = d; nrms[k] = s; }
    }
    __syncthreads();

    if (warp == 0) {
        const int ka = lane, kb = lane + 32;
        float cosA = -1e30f, cosB = -1e30f;
        if (ka < KT) cosA = dots[ka] / (cn * fmaxf(sqrtf(nrms[ka]), EPS));
        if (kb < KT) cosB = dots[kb] / (cn * fmaxf(sqrtf(nrms[kb]), EPS));
        float m = fmaxf(cosA, cosB);
        #pragma unroll
        for (int o = 16; o; o >>= 1) m = fmaxf(m, __shfl_xor_sync(0xFFFFFFFFu, m, o));
        float eA = (ka < KT) ? __expf(cosA - m) : 0.f;
        float eB = (kb < KT) ? __expf(cosB - m) : 0.f;
        const float inv = 1.f / wred_sum(eA + eB);
        if (ka < KT) wgt[ka] = eA * inv;
        if (kb < KT) wgt[kb] = eB * inv;
    }
    __syncthreads();

    float acc = 0.f;
    for (int k = 0; k < KT; k++)
        acc = fmaf(wgt[k], nb_s[k * H + tid], acc);
    const float rr = acc + c;

    g_rr[(size_t)b * H + tid] = __float2half(rr);

    const int lbl = labels[b];
    atomicAdd(&g_csum_r[0][lbl * H + tid], rr);
    if (tid == 0) atomicAdd(&g_ccnt_r[0][lbl], 1.f);
}

// ---------------------------------------------------------------------------
extern "C" void kernel_launch(void* const* d_in, const int* in_sizes, int n_in,
                              void* d_out, int out_size) {
    const float* embeds = (const float*)d_in[0];
    const float* wself  = (const float*)d_in[1];
    const float* wnb    = (const float*)d_in[2];
    const float* wnb2   = (const float*)d_in[3];
    const int*   idx    = (const int*)d_in[4];
    const int*   labels = (const int*)d_in[5];
    const int*   nbr    = (const int*)d_in[6];
    const int*   nbr2   = (const int*)d_in[7];
    float* out = (float*)d_out;

    const int B  = in_sizes[4];
    const int K1 = in_sizes[6] / B;
    const int K2 = in_sizes[7] / B;
    const int KT = K1 + K2;
    const int N  = in_sizes[0] / H;

    if (K1 == 16 && K2 == 32 && N <= N_MAX && B <= B_MAX) {
        kc<<<2048, 256>>>(embeds, wnb, wnb2, N);
        k1s<16, 32><<<B, 128>>>(wself, wnb, wnb2, idx, labels, nbr, nbr2);
    } else {
        const size_t smem = (size_t)(KT * H + H + 3 * KT + 32) * sizeof(float);
        cudaFuncSetAttribute(k1g, cudaFuncAttributeMaxDynamicSharedMemorySize, (int)smem);
        kzf<<<NB_CLASSES, 256>>>();
        k1g<<<B, 256, smem>>>(embeds, wself, wnb, wnb2, idx, labels, nbr, nbr2, K1, K2);
    }
    k2r<<<NB_CLASSES, 256>>>();
    k3<<<(B + 7) / 8, 256>>>(out, B);
}

// round 16
// speedup vs baseline: 1.0378x; 1.0378x over previous
#include <cuda_runtime.h>
#include <cuda_fp16.h>
#include <math.h>

#define H 256
#define NB_CLASSES 7
#define B_MAX 14000
#define N_MAX 100000
#define EPS 1e-8f
#define NREP 16

// Scratch (allocation-free rule: __device__ globals)
__device__ __align__(16) __half g_eh[(size_t)N_MAX * H];  // fp16 embeds (51.2 MB)
__device__ float g_n1[N_MAX];                             // ||e * w_nb||^2
__device__ float g_n2[N_MAX];                             // ||e * w_nb2||^2
__device__ __align__(16) __half g_rr[(size_t)B_MAX * H];  // rawret fp16 (7.2 MB)
__device__ __align__(8) float g_csum_r[NREP][NB_CLASSES * H];  // replicated sums
__device__ float g_ccnt_r[NREP][NB_CLASSES];
__device__ __align__(16) __half g_avh[NB_CLASSES * H];    // (ave/an) fp16

__device__ __forceinline__ float wred_sum(float v) {
    #pragma unroll
    for (int o = 16; o; o >>= 1) v += __shfl_xor_sync(0xFFFFFFFFu, v, o);
    return v;
}

// ---------------------------------------------------------------------------
// Kernel C (R14 form): fp32 -> fp16 table + per-row weighted norms.
// Warp per 2 rows. Blocks 0..15 zero their replica accumulator.
// ---------------------------------------------------------------------------
__global__ void kc(const float* __restrict__ embeds,
                   const float* __restrict__ wnb,
                   const float* __restrict__ wnb2,
                   int N) {
    if (blockIdx.x < NREP) {
        float* cs = g_csum_r[blockIdx.x];
        for (int j = threadIdx.x; j < NB_CLASSES * H; j += blockDim.x) cs[j] = 0.f;
        if (threadIdx.x < NB_CLASSES) g_ccnt_r[blockIdx.x][threadIdx.x] = 0.f;
    }
    const int lane = threadIdx.x & 31;
    const int gw = (blockIdx.x * blockDim.x + threadIdx.x) >> 5;
    const int nw = (gridDim.x * blockDim.x) >> 5;

    const float4 wa0 = ((const float4*)wnb)[2 * lane];
    const float4 wa1 = ((const float4*)wnb)[2 * lane + 1];
    const float4 wb0 = ((const float4*)wnb2)[2 * lane];
    const float4 wb1 = ((const float4*)wnb2)[2 * lane + 1];
    float wav[8] = {wa0.x, wa0.y, wa0.z, wa0.w, wa1.x, wa1.y, wa1.z, wa1.w};
    float wbv[8] = {wb0.x, wb0.y, wb0.z, wb0.w, wb1.x, wb1.y, wb1.z, wb1.w};

    for (int r = gw; r < N; r += 2 * nw) {
        const int r2 = r + nw;
        const bool h2 = (r2 < N);

        const float4* s0 = (const float4*)(embeds + (size_t)r * H);
        const float4 a0 = s0[2 * lane];
        const float4 b0 = s0[2 * lane + 1];
        float4 a1, b1;
        if (h2) {
            const float4* s1 = (const float4*)(embeds + (size_t)r2 * H);
            a1 = s1[2 * lane];
            b1 = s1[2 * lane + 1];
        }

        float eA[8] = {a0.x, a0.y, a0.z, a0.w, b0.x, b0.y, b0.z, b0.w};
        float n1a = 0.f, n2a = 0.f;
        #pragma unroll
        for (int i = 0; i < 8; i++) {
            const float x1 = eA[i] * wav[i];
            const float x2 = eA[i] * wbv[i];
            n1a = fmaf(x1, x1, n1a);
            n2a = fmaf(x2, x2, n2a);
        }
        union { uint4 u; __half2 h[4]; } pA;
        #pragma unroll
        for (int i = 0; i < 4; i++)
            pA.h[i] = __float22half2_rn(make_float2(eA[2 * i], eA[2 * i + 1]));
        ((uint4*)(g_eh + (size_t)r * H))[lane] = pA.u;

        float n1b = 0.f, n2b = 0.f;
        if (h2) {
            float eB[8] = {a1.x, a1.y, a1.z, a1.w, b1.x, b1.y, b1.z, b1.w};
            #pragma unroll
            for (int i = 0; i < 8; i++) {
                const float x1 = eB[i] * wav[i];
                const float x2 = eB[i] * wbv[i];
                n1b = fmaf(x1, x1, n1b);
                n2b = fmaf(x2, x2, n2b);
            }
            union { uint4 u; __half2 h[4]; } pB;
            #pragma unroll
            for (int i = 0; i < 4; i++)
                pB.h[i] = __float22half2_rn(make_float2(eB[2 * i], eB[2 * i + 1]));
            ((uint4*)(g_eh + (size_t)r2 * H))[lane] = pB.u;
        }

        #pragma unroll
        for (int o = 16; o; o >>= 1) {
            n1a += __shfl_xor_sync(0xFFFFFFFFu, n1a, o);
            n2a += __shfl_xor_sync(0xFFFFFFFFu, n2a, o);
            n1b += __shfl_xor_sync(0xFFFFFFFFu, n1b, o);
            n2b += __shfl_xor_sync(0xFFFFFFFFu, n2b, o);
        }
        if (lane == 0) {
            g_n1[r] = n1a; g_n2[r] = n2a;
            if (h2) { g_n1[r2] = n1b; g_n2[r2] = n2b; }
        }
    }
}

// ---------------------------------------------------------------------------
// Kernel 1 (K1=16, K2=32): 1 CTA per row b, 128 threads (4 warps), occ 8.
// R14 structure; ONLY change: wsum weights read as float4 broadcast chunks
// (1 wavefront per 4 rows instead of 4).
// ---------------------------------------------------------------------------
template<int K1, int K2>
__global__ void __launch_bounds__(128, 8)
k1s(const float* __restrict__ wself,
    const float* __restrict__ wnb,
    const float* __restrict__ wnb2,
    const int* __restrict__ idx,
    const int* __restrict__ labels,
    const int* __restrict__ nbr,
    const int* __restrict__ nbr2) {
    constexpr int KT = K1 + K2;   // 48
    constexpr int JP = KT / 4;    // 12 rows per warp
    constexpr int J1 = K1 / 4;    // 4: first J1 j's are 1-hop

    __shared__ __align__(16) __half nb_h[KT * H];  // raw fp16 rows (24.6 KB)
    __shared__ float nrm_s[KT];
    __shared__ float dots[KT];
    __shared__ __align__(16) float wgt[4][KT];     // per-warp softmax weights

    const int b    = blockIdx.x;
    const int tid  = threadIdx.x;
    const int lane = tid & 31;
    const int warp = tid >> 5;

    int rows[JP];
    #pragma unroll
    for (int j = 0; j < JP; j++) {
        const int k = warp + 4 * j;
        rows[j] = (j < J1) ? __ldg(&nbr[b * K1 + k]) : __ldg(&nbr2[b * K2 + k - K1]);
    }
    #pragma unroll
    for (int j = 0; j < JP; j++) {
        const int k = warp + 4 * j;
        const __half* gp = g_eh + (size_t)rows[j] * H + lane * 8;
        const unsigned sp = (unsigned)__cvta_generic_to_shared(nb_h + k * H + lane * 8);
        asm volatile("cp.async.cg.shared.global [%0], [%1], 16;\n"
                     :: "r"(sp), "l"(gp) : "memory");
    }
    asm volatile("cp.async.commit_group;\n" ::: "memory");

    if (tid < KT) {
        const int r = (tid < K1) ? nbr[b * K1 + tid] : nbr2[b * K2 + tid - K1];
        nrm_s[tid] = (tid < K1) ? g_n1[r] : g_n2[r];
    }

    const int crow = idx[b];
    const int lbl  = labels[b];

    float c1v[8], c2v[8];
    float cn;
    {
        union { uint4 u; __half2 h[4]; } cr;
        cr.u = ((const uint4*)(g_eh + (size_t)crow * H))[lane];
        const float4 ws0 = ((const float4*)wself)[2 * lane];
        const float4 ws1 = ((const float4*)wself)[2 * lane + 1];
        const float wsv[8] = {ws0.x, ws0.y, ws0.z, ws0.w, ws1.x, ws1.y, ws1.z, ws1.w};
        const float2 e0 = __half22float2(cr.h[0]);
        const float2 e1 = __half22float2(cr.h[1]);
        const float2 e2 = __half22float2(cr.h[2]);
        const float2 e3 = __half22float2(cr.h[3]);
        const float ce[8] = {e0.x, e0.y, e1.x, e1.y, e2.x, e2.y, e3.x, e3.y};

        float cvs[8];
        float cs = 0.f;
        #pragma unroll
        for (int i = 0; i < 8; i++) {
            cvs[i] = ce[i] * wsv[i];
            cs = fmaf(cvs[i], cvs[i], cs);
        }
        cn = fmaxf(sqrtf(wred_sum(cs)), EPS);

        const float4 wa0 = ((const float4*)wnb)[2 * lane];
        const float4 wa1 = ((const float4*)wnb)[2 * lane + 1];
        const float4 wb0 = ((const float4*)wnb2)[2 * lane];
        const float4 wb1 = ((const float4*)wnb2)[2 * lane + 1];
        const float wav[8] = {wa0.x, wa0.y, wa0.z, wa0.w, wa1.x, wa1.y, wa1.z, wa1.w};
        const float wbv[8] = {wb0.x, wb0.y, wb0.z, wb0.w, wb1.x, wb1.y, wb1.z, wb1.w};
        #pragma unroll
        for (int i = 0; i < 8; i++) {
            c1v[i] = cvs[i] * wav[i];
            c2v[i] = cvs[i] * wbv[i];
        }
    }

    const float2 ws2 = ((const float2*)wself)[tid];
    const float2 ev2 = __half22float2(((const __half2*)(g_eh + (size_t)crow * H))[tid]);
    const float2 cv = make_float2(ev2.x * ws2.x, ev2.y * ws2.y);

    asm volatile("cp.async.wait_group 0;\n" ::: "memory");

    float d[JP];
    #pragma unroll
    for (int j = 0; j < JP; j++) {
        const int k = warp + 4 * j;
        union { uint4 u; __half2 h[4]; } pk;
        pk.u = ((const uint4*)(nb_h + k * H))[lane];
        const float* cw = (j < J1) ? c1v : c2v;
        const float2 v0 = __half22float2(pk.h[0]);
        const float2 v1 = __half22float2(pk.h[1]);
        const float2 v2 = __half22float2(pk.h[2]);
        const float2 v3 = __half22float2(pk.h[3]);
        d[j] = v0.x * cw[0] + v0.y * cw[1] + v1.x * cw[2] + v1.y * cw[3]
             + v2.x * cw[4] + v2.y * cw[5] + v3.x * cw[6] + v3.y * cw[7];
    }
    #pragma unroll
    for (int o = 16; o; o >>= 1) {
        #pragma unroll
        for (int j = 0; j < JP; j++)
            d[j] += __shfl_xor_sync(0xFFFFFFFFu, d[j], o);
    }
    if (lane == 0) {
        #pragma unroll
        for (int j = 0; j < JP; j++) dots[warp + 4 * j] = d[j];
    }
    __syncthreads();   // THE barrier

    {
        const int ka = lane, kb = lane + 32;
        const float cosA = dots[ka] / (cn * fmaxf(sqrtf(nrm_s[ka]), EPS));
        const float cosB = (kb < KT)
            ? dots[kb] / (cn * fmaxf(sqrtf(nrm_s[kb]), EPS)) : -1e30f;
        float m = fmaxf(cosA, cosB);
        #pragma unroll
        for (int o = 16; o; o >>= 1) m = fmaxf(m, __shfl_xor_sync(0xFFFFFFFFu, m, o));
        const float eA = __expf(cosA - m);
        const float eB = (kb < KT) ? __expf(cosB - m) : 0.f;
        const float inv = 1.f / wred_sum(eA + eB);
        wgt[warp][ka] = eA * inv;
        if (kb < KT) wgt[warp][kb] = eB * inv;
    }
    __syncwarp();

    // --- weighted sum: float4 weight chunks (1 broadcast wf per 4 rows) ---
    const float* wg = wgt[warp];
    float ax = 0.f, ay = 0.f, bx = 0.f, by = 0.f;
    #pragma unroll
    for (int k4 = 0; k4 < K1; k4 += 4) {
        const float4 wq = *((const float4*)(wg + k4));
        const float2 va = __half22float2(((const __half2*)(nb_h + (k4 + 0) * H))[tid]);
        ax = fmaf(wq.x, va.x, ax); ay = fmaf(wq.x, va.y, ay);
        const float2 vb = __half22float2(((const __half2*)(nb_h + (k4 + 1) * H))[tid]);
        ax = fmaf(wq.y, vb.x, ax); ay = fmaf(wq.y, vb.y, ay);
        const float2 vc = __half22float2(((const __half2*)(nb_h + (k4 + 2) * H))[tid]);
        ax = fmaf(wq.z, vc.x, ax); ay = fmaf(wq.z, vc.y, ay);
        const float2 vd = __half22float2(((const __half2*)(nb_h + (k4 + 3) * H))[tid]);
        ax = fmaf(wq.w, vd.x, ax); ay = fmaf(wq.w, vd.y, ay);
    }
    #pragma unroll
    for (int k4 = K1; k4 < KT; k4 += 4) {
        const float4 wq = *((const float4*)(wg + k4));
        const float2 va = __half22float2(((const __half2*)(nb_h + (k4 + 0) * H))[tid]);
        bx = fmaf(wq.x, va.x, bx); by = fmaf(wq.x, va.y, by);
        const float2 vb = __half22float2(((const __half2*)(nb_h + (k4 + 1) * H))[tid]);
        bx = fmaf(wq.y, vb.x, bx); by = fmaf(wq.y, vb.y, by);
        const float2 vc = __half22float2(((const __half2*)(nb_h + (k4 + 2) * H))[tid]);
        bx = fmaf(wq.z, vc.x, bx); by = fmaf(wq.z, vc.y, by);
        const float2 vd = __half22float2(((const __half2*)(nb_h + (k4 + 3) * H))[tid]);
        bx = fmaf(wq.w, vd.x, bx); by = fmaf(wq.w, vd.y, by);
    }
    const float2 wa = ((const float2*)wnb)[tid];
    const float2 wb = ((const float2*)wnb2)[tid];
    const float rx = ax * wa.x + bx * wb.x + cv.x;
    const float ry = ay * wa.y + by * wb.y + cv.y;

    ((__half2*)g_rr)[(size_t)b * (H / 2) + tid] =
        __float22half2_rn(make_float2(rx, ry));

    float* csr = g_csum_r[b & (NREP - 1)];
    atomicAdd((float2*)&csr[lbl * H + 2 * tid], make_float2(rx, ry));
    if (tid == 0) atomicAdd(&g_ccnt_r[b & (NREP - 1)][lbl], 1.f);
}

// ---------------------------------------------------------------------------
// Kernel 2r: fold replicas -> per-class mean -> norm -> g_avh = fp16(ave/an).
// ---------------------------------------------------------------------------
__global__ void k2r() {
    __shared__ float red[8];
    const int cc   = blockIdx.x;
    const int t    = threadIdx.x;
    const int lane = t & 31;
    const int warp = t >> 5;

    float s = 0.f;
    #pragma unroll
    for (int r = 0; r < NREP; r++) s += g_csum_r[r][cc * H + t];
    float cnt = 0.f;
    #pragma unroll
    for (int r = 0; r < NREP; r++) cnt += g_ccnt_r[r][cc];
    const float mean = s / fmaxf(cnt, 1.f);

    float sq = wred_sum(mean * mean);
    if (lane == 0) red[warp] = sq;
    __syncthreads();
    float an = 0.f;
    #pragma unroll
    for (int i = 0; i < 8; i++) an += red[i];
    an = fmaxf(sqrtf(an), EPS);

    g_avh[cc * H + t] = __float2half(mean / an);
}

// ---------------------------------------------------------------------------
// Kernel 3: output. 1750 CTAs x 256 threads; ONE WARP PER ROW.
// ---------------------------------------------------------------------------
__global__ void __launch_bounds__(256)
k3(float* __restrict__ out, int B) {
    __shared__ __align__(16) __half avh_s[NB_CLASSES * H];
    const int tid  = threadIdx.x;
    const int lane = tid & 31;
    const int warp = tid >> 5;

    for (int i = tid; i < NB_CLASSES * H / 8; i += 256)
        ((uint4*)avh_s)[i] = ((const uint4*)g_avh)[i];
    __syncthreads();

    const int b = blockIdx.x * 8 + warp;
    if (b >= B) return;

    union { uint4 u; __half2 h[4]; } pk;
    pk.u = ((const uint4*)(g_rr + (size_t)b * H))[lane];
    const float2 v0 = __half22float2(pk.h[0]);
    const float2 v1 = __half22float2(pk.h[1]);
    const float2 v2 = __half22float2(pk.h[2]);
    const float2 v3 = __half22float2(pk.h[3]);

    float d[NB_CLASSES];
    #pragma unroll
    for (int cc = 0; cc < NB_CLASSES; cc++) {
        union { uint4 u; __half2 h[4]; } av;
        av.u = ((const uint4*)(avh_s + cc * H))[lane];
        const float2 a0 = __half22float2(av.h[0]);
        const float2 a1 = __half22float2(av.h[1]);
        const float2 a2 = __half22float2(av.h[2]);
        const float2 a3 = __half22float2(av.h[3]);
        d[cc] = v0.x * a0.x + v0.y * a0.y + v1.x * a1.x + v1.y * a1.y
              + v2.x * a2.x + v2.y * a2.y + v3.x * a3.x + v3.y * a3.y;
    }
    float rsq = v0.x * v0.x + v0.y * v0.y + v1.x * v1.x + v1.y * v1.y
              + v2.x * v2.x + v2.y * v2.y + v3.x * v3.x + v3.y * v3.y;

    #pragma unroll
    for (int o = 16; o; o >>= 1) {
        #pragma unroll
        for (int cc = 0; cc < NB_CLASSES; cc++)
            d[cc] += __shfl_xor_sync(0xFFFFFFFFu, d[cc], o);
        rsq += __shfl_xor_sync(0xFFFFFFFFu, rsq, o);
    }
    const float inv_rbn = 1.f / fmaxf(sqrtf(rsq), EPS);

    float m = -1e30f;
    #pragma unroll
    for (int cc = 0; cc < NB_CLASSES; cc++) {
        d[cc] *= inv_rbn;
        m = fmaxf(m, d[cc]);
    }
    float s = 0.f;
    #pragma unroll
    for (int cc = 0; cc < NB_CLASSES; cc++) {
        d[cc] = __expf(d[cc] - m);
        s += d[cc];
    }
    const float inv = 1.f / s;
    if (lane < NB_CLASSES) {
        float v = 0.f;
        #pragma unroll
        for (int cc = 0; cc < NB_CLASSES; cc++)
            if (lane == cc) v = d[cc] * inv;
        out[b * NB_CLASSES + lane] = v;
    }
}

// ---------------------------------------------------------------------------
// Generic fallback (any K1/K2), fp32 path -> replica 0
// ---------------------------------------------------------------------------
__global__ void kzf() {
    const int i = blockIdx.x * blockDim.x + threadIdx.x;
    if (i < NB_CLASSES * H) {
        #pragma unroll
        for (int r = 0; r < NREP; r++) g_csum_r[r][i] = 0.f;
    }
    if (i < NB_CLASSES) {
        #pragma unroll
        for (int r = 0; r < NREP; r++) g_ccnt_r[r][i] = 0.f;
    }
}

__global__ void k1g(const float* __restrict__ embeds,
                    const float* __restrict__ wself,
                    const float* __restrict__ wnb,
                    const float* __restrict__ wnb2,
                    const int* __restrict__ idx,
                    const int* __restrict__ labels,
                    const int* __restrict__ nbr,
                    const int* __restrict__ nbr2,
                    int K1, int K2) {
    extern __shared__ float sh[];
    const int KT = K1 + K2;
    float* nb_s = sh;
    float* cen  = sh + KT * H;
    float* dots = cen + H;
    float* nrms = dots + KT;
    float* wgt  = nrms + KT;
    float* red  = wgt + KT;

    const int b    = blockIdx.x;
    const int tid  = threadIdx.x;
    const int lane = tid & 31;
    const int warp = tid >> 5;

    const int crow = idx[b];
    const float c = embeds[(size_t)crow * H + tid] * wself[tid];
    cen[tid] = c;
    float cs = wred_sum(c * c);
    if (lane == 0) red[warp] = cs;
    __syncthreads();

    float cn = 0.f;
    #pragma unroll
    for (int i = 0; i < 8; i++) cn += red[i];
    cn = fmaxf(sqrtf(cn), EPS);

    const float4* cen4 = (const float4*)cen;
    const float4 c0 = cen4[lane];
    const float4 c1 = cen4[lane + 32];

    for (int k = warp; k < KT; k += 8) {
        const int r = (k < K1) ? nbr[b * K1 + k] : nbr2[b * K2 + (k - K1)];
        const float4* src = (const float4*)(embeds + (size_t)r * H);
        const float4* wv  = (const float4*)((k < K1) ? wnb : wnb2);
        float4 e0 = src[lane];
        float4 e1 = src[lane + 32];
        const float4 w0 = wv[lane];
        const float4 w1 = wv[lane + 32];
        e0.x *= w0.x; e0.y *= w0.y; e0.z *= w0.z; e0.w *= w0.w;
        e1.x *= w1.x; e1.y *= w1.y; e1.z *= w1.z; e1.w *= w1.w;

        float d = e0.x * c0.x + e0.y * c0.y + e0.z * c0.z + e0.w * c0.w
                + e1.x * c1.x + e1.y * c1.y + e1.z * c1.z + e1.w * c1.w;
        float s = e0.x * e0.x + e0.y * e0.y + e0.z * e0.z + e0.w * e0.w
                + e1.x * e1.x + e1.y * e1.y + e1.z * e1.z + e1.w * e1.w;

        float4* dst = (float4*)(nb_s + k * H);
        dst[lane]      = e0;
        dst[lane + 32] = e1;

        d = wred_sum(d);
        s = wred_sum(s);
        if (lane == 0) { dots[k] = d; nrms[k] = s; }
    }
    __syncthreads();

    if (warp == 0) {
        const int ka = lane, kb = lane + 32;
        float cosA = -1e30f, cosB = -1e30f;
        if (ka < KT) cosA = dots[ka] / (cn * fmaxf(sqrtf(nrms[ka]), EPS));
        if (kb < KT) cosB = dots[kb] / (cn * fmaxf(sqrtf(nrms[kb]), EPS));
        float m = fmaxf(cosA, cosB);
        #pragma unroll
        for (int o = 16; o; o >>= 1) m = fmaxf(m, __shfl_xor_sync(0xFFFFFFFFu, m, o));
        float eA = (ka < KT) ? __expf(cosA - m) : 0.f;
        float eB = (kb < KT) ? __expf(cosB - m) : 0.f;
        const float inv = 1.f / wred_sum(eA + eB);
        if (ka < KT) wgt[ka] = eA * inv;
        if (kb < KT) wgt[kb] = eB * inv;
    }
    __syncthreads();

    float acc = 0.f;
    for (int k = 0; k < KT; k++)
        acc = fmaf(wgt[k], nb_s[k * H + tid], acc);
    const float rr = acc + c;

    g_rr[(size_t)b * H + tid] = __float2half(rr);

    const int lbl = labels[b];
    atomicAdd(&g_csum_r[0][lbl * H + tid], rr);
    if (tid == 0) atomicAdd(&g_ccnt_r[0][lbl], 1.f);
}

// ---------------------------------------------------------------------------
extern "C" void kernel_launch(void* const* d_in, const int* in_sizes, int n_in,
                              void* d_out, int out_size) {
    const float* embeds = (const float*)d_in[0];
    const float* wself  = (const float*)d_in[1];
    const float* wnb    = (const float*)d_in[2];
    const float* wnb2   = (const float*)d_in[3];
    const int*   idx    = (const int*)d_in[4];
    const int*   labels = (const int*)d_in[5];
    const int*   nbr    = (const int*)d_in[6];
    const int*   nbr2   = (const int*)d_in[7];
    float* out = (float*)d_out;

    const int B  = in_sizes[4];
    const int K1 = in_sizes[6] / B;
    const int K2 = in_sizes[7] / B;
    const int KT = K1 + K2;
    const int N  = in_sizes[0] / H;

    if (K1 == 16 && K2 == 32 && N <= N_MAX && B <= B_MAX) {
        kc<<<2048, 256>>>(embeds, wnb, wnb2, N);
        k1s<16, 32><<<B, 128>>>(wself, wnb, wnb2, idx, labels, nbr, nbr2);
    } else {
        const size_t smem = (size_t)(KT * H + H + 3 * KT + 32) * sizeof(float);
        cudaFuncSetAttribute(k1g, cudaFuncAttributeMaxDynamicSharedMemorySize, (int)smem);
        kzf<<<NB_CLASSES, 256>>>();
        k1g<<<B, 256, smem>>>(embeds, wself, wnb, wnb2, idx, labels, nbr, nbr2, K1, K2);
    }
    k2r<<<NB_CLASSES, 256>>>();
    k3<<<(B + 7) / 8, 256>>>(out, B);
}

// round 17
// speedup vs baseline: 1.0804x; 1.0410x over previous
#include <cuda_runtime.h>
#include <cuda_fp16.h>
#include <math.h>

#define H 256
#define NB_CLASSES 7
#define B_MAX 14000
#define N_MAX 100000
#define EPS 1e-8f
#define NREP 16

// Scratch (allocation-free rule: __device__ globals)
__device__ __align__(16) __half g_eh[(size_t)N_MAX * H];  // fp16 embeds (51.2 MB)
__device__ float g_n1[N_MAX];                             // ||e * w_nb||^2
__device__ float g_n2[N_MAX];                             // ||e * w_nb2||^2
__device__ __align__(16) __half g_rr[(size_t)B_MAX * H];  // rawret fp16 (7.2 MB)
__device__ __align__(8) float g_csum_r[NREP][NB_CLASSES * H];  // replicated sums
__device__ float g_ccnt_r[NREP][NB_CLASSES];
__device__ __align__(16) __half g_avh[NB_CLASSES * H];    // (ave/an) fp16

__device__ __forceinline__ float wred_sum(float v) {
    #pragma unroll
    for (int o = 16; o; o >>= 1) v += __shfl_xor_sync(0xFFFFFFFFu, v, o);
    return v;
}

// ---------------------------------------------------------------------------
// Kernel C (R14 form + __ldcs): fp32 -> fp16 table + per-row weighted norms.
// Warp per 2 rows. Blocks 0..15 zero their replica accumulator.
// ---------------------------------------------------------------------------
__global__ void kc(const float* __restrict__ embeds,
                   const float* __restrict__ wnb,
                   const float* __restrict__ wnb2,
                   int N) {
    if (blockIdx.x < NREP) {
        float* cs = g_csum_r[blockIdx.x];
        for (int j = threadIdx.x; j < NB_CLASSES * H; j += blockDim.x) cs[j] = 0.f;
        if (threadIdx.x < NB_CLASSES) g_ccnt_r[blockIdx.x][threadIdx.x] = 0.f;
    }
    const int lane = threadIdx.x & 31;
    const int gw = (blockIdx.x * blockDim.x + threadIdx.x) >> 5;
    const int nw = (gridDim.x * blockDim.x) >> 5;

    const float4 wa0 = ((const float4*)wnb)[2 * lane];
    const float4 wa1 = ((const float4*)wnb)[2 * lane + 1];
    const float4 wb0 = ((const float4*)wnb2)[2 * lane];
    const float4 wb1 = ((const float4*)wnb2)[2 * lane + 1];
    float wav[8] = {wa0.x, wa0.y, wa0.z, wa0.w, wa1.x, wa1.y, wa1.z, wa1.w};
    float wbv[8] = {wb0.x, wb0.y, wb0.z, wb0.w, wb1.x, wb1.y, wb1.z, wb1.w};

    for (int r = gw; r < N; r += 2 * nw) {
        const int r2 = r + nw;
        const bool h2 = (r2 < N);

        const float4* s0 = (const float4*)(embeds + (size_t)r * H);
        const float4 a0 = __ldcs(&s0[2 * lane]);
        const float4 b0 = __ldcs(&s0[2 * lane + 1]);
        float4 a1, b1;
        if (h2) {
            const float4* s1 = (const float4*)(embeds + (size_t)r2 * H);
            a1 = __ldcs(&s1[2 * lane]);
            b1 = __ldcs(&s1[2 * lane + 1]);
        }

        float eA[8] = {a0.x, a0.y, a0.z, a0.w, b0.x, b0.y, b0.z, b0.w};
        float n1a = 0.f, n2a = 0.f;
        #pragma unroll
        for (int i = 0; i < 8; i++) {
            const float x1 = eA[i] * wav[i];
            const float x2 = eA[i] * wbv[i];
            n1a = fmaf(x1, x1, n1a);
            n2a = fmaf(x2, x2, n2a);
        }
        union { uint4 u; __half2 h[4]; } pA;
        #pragma unroll
        for (int i = 0; i < 4; i++)
            pA.h[i] = __float22half2_rn(make_float2(eA[2 * i], eA[2 * i + 1]));
        ((uint4*)(g_eh + (size_t)r * H))[lane] = pA.u;

        float n1b = 0.f, n2b = 0.f;
        if (h2) {
            float eB[8] = {a1.x, a1.y, a1.z, a1.w, b1.x, b1.y, b1.z, b1.w};
            #pragma unroll
            for (int i = 0; i < 8; i++) {
                const float x1 = eB[i] * wav[i];
                const float x2 = eB[i] * wbv[i];
                n1b = fmaf(x1, x1, n1b);
                n2b = fmaf(x2, x2, n2b);
            }
            union { uint4 u; __half2 h[4]; } pB;
            #pragma unroll
            for (int i = 0; i < 4; i++)
                pB.h[i] = __float22half2_rn(make_float2(eB[2 * i], eB[2 * i + 1]));
            ((uint4*)(g_eh + (size_t)r2 * H))[lane] = pB.u;
        }

        #pragma unroll
        for (int o = 16; o; o >>= 1) {
            n1a += __shfl_xor_sync(0xFFFFFFFFu, n1a, o);
            n2a += __shfl_xor_sync(0xFFFFFFFFu, n2a, o);
            n1b += __shfl_xor_sync(0xFFFFFFFFu, n1b, o);
            n2b += __shfl_xor_sync(0xFFFFFFFFu, n2b, o);
        }
        if (lane == 0) {
            g_n1[r] = n1a; g_n2[r] = n2a;
            if (h2) { g_n1[r2] = n1b; g_n2[r2] = n2b; }
        }
    }
}

// ---------------------------------------------------------------------------
// Kernel 1 (K1=16, K2=32): 1 CTA per row b, 128 threads (4 warps), occ 9.
// R16 structure; changes: single shared wgt[KT] (all warps write identical
// values -> 576B SMEM saved), __launch_bounds__(128, 9).
// ---------------------------------------------------------------------------
template<int K1, int K2>
__global__ void __launch_bounds__(128, 9)
k1s(const float* __restrict__ wself,
    const float* __restrict__ wnb,
    const float* __restrict__ wnb2,
    const int* __restrict__ idx,
    const int* __restrict__ labels,
    const int* __restrict__ nbr,
    const int* __restrict__ nbr2) {
    constexpr int KT = K1 + K2;   // 48
    constexpr int JP = KT / 4;    // 12 rows per warp
    constexpr int J1 = K1 / 4;    // 4: first J1 j's are 1-hop

    __shared__ __align__(16) __half nb_h[KT * H];  // raw fp16 rows (24.6 KB)
    __shared__ float nrm_s[KT];
    __shared__ float dots[KT];
    __shared__ __align__(16) float wgt[KT];        // shared softmax weights

    const int b    = blockIdx.x;
    const int tid  = threadIdx.x;
    const int lane = tid & 31;
    const int warp = tid >> 5;

    int rows[JP];
    #pragma unroll
    for (int j = 0; j < JP; j++) {
        const int k = warp + 4 * j;
        rows[j] = (j < J1) ? __ldg(&nbr[b * K1 + k]) : __ldg(&nbr2[b * K2 + k - K1]);
    }
    #pragma unroll
    for (int j = 0; j < JP; j++) {
        const int k = warp + 4 * j;
        const __half* gp = g_eh + (size_t)rows[j] * H + lane * 8;
        const unsigned sp = (unsigned)__cvta_generic_to_shared(nb_h + k * H + lane * 8);
        asm volatile("cp.async.cg.shared.global [%0], [%1], 16;\n"
                     :: "r"(sp), "l"(gp) : "memory");
    }
    asm volatile("cp.async.commit_group;\n" ::: "memory");

    if (tid < KT) {
        const int r = (tid < K1) ? nbr[b * K1 + tid] : nbr2[b * K2 + tid - K1];
        nrm_s[tid] = (tid < K1) ? g_n1[r] : g_n2[r];
    }

    const int crow = idx[b];
    const int lbl  = labels[b];

    float c1v[8], c2v[8];
    float cn;
    {
        union { uint4 u; __half2 h[4]; } cr;
        cr.u = ((const uint4*)(g_eh + (size_t)crow * H))[lane];
        const float4 ws0 = ((const float4*)wself)[2 * lane];
        const float4 ws1 = ((const float4*)wself)[2 * lane + 1];
        const float wsv[8] = {ws0.x, ws0.y, ws0.z, ws0.w, ws1.x, ws1.y, ws1.z, ws1.w};
        const float2 e0 = __half22float2(cr.h[0]);
        const float2 e1 = __half22float2(cr.h[1]);
        const float2 e2 = __half22float2(cr.h[2]);
        const float2 e3 = __half22float2(cr.h[3]);
        const float ce[8] = {e0.x, e0.y, e1.x, e1.y, e2.x, e2.y, e3.x, e3.y};

        float cvs[8];
        float cs = 0.f;
        #pragma unroll
        for (int i = 0; i < 8; i++) {
            cvs[i] = ce[i] * wsv[i];
            cs = fmaf(cvs[i], cvs[i], cs);
        }
        cn = fmaxf(sqrtf(wred_sum(cs)), EPS);

        const float4 wa0 = ((const float4*)wnb)[2 * lane];
        const float4 wa1 = ((const float4*)wnb)[2 * lane + 1];
        const float4 wb0 = ((const float4*)wnb2)[2 * lane];
        const float4 wb1 = ((const float4*)wnb2)[2 * lane + 1];
        const float wav[8] = {wa0.x, wa0.y, wa0.z, wa0.w, wa1.x, wa1.y, wa1.z, wa1.w};
        const float wbv[8] = {wb0.x, wb0.y, wb0.z, wb0.w, wb1.x, wb1.y, wb1.z, wb1.w};
        #pragma unroll
        for (int i = 0; i < 8; i++) {
            c1v[i] = cvs[i] * wav[i];
            c2v[i] = cvs[i] * wbv[i];
        }
    }

    const float2 ws2 = ((const float2*)wself)[tid];
    const float2 ev2 = __half22float2(((const __half2*)(g_eh + (size_t)crow * H))[tid]);
    const float2 cv = make_float2(ev2.x * ws2.x, ev2.y * ws2.y);

    asm volatile("cp.async.wait_group 0;\n" ::: "memory");

    float d[JP];
    #pragma unroll
    for (int j = 0; j < JP; j++) {
        const int k = warp + 4 * j;
        union { uint4 u; __half2 h[4]; } pk;
        pk.u = ((const uint4*)(nb_h + k * H))[lane];
        const float* cw = (j < J1) ? c1v : c2v;
        const float2 v0 = __half22float2(pk.h[0]);
        const float2 v1 = __half22float2(pk.h[1]);
        const float2 v2 = __half22float2(pk.h[2]);
        const float2 v3 = __half22float2(pk.h[3]);
        d[j] = v0.x * cw[0] + v0.y * cw[1] + v1.x * cw[2] + v1.y * cw[3]
             + v2.x * cw[4] + v2.y * cw[5] + v3.x * cw[6] + v3.y * cw[7];
    }
    #pragma unroll
    for (int o = 16; o; o >>= 1) {
        #pragma unroll
        for (int j = 0; j < JP; j++)
            d[j] += __shfl_xor_sync(0xFFFFFFFFu, d[j], o);
    }
    if (lane == 0) {
        #pragma unroll
        for (int j = 0; j < JP; j++) dots[warp + 4 * j] = d[j];
    }
    __syncthreads();   // THE barrier

    // per-warp redundant softmax; all warps write IDENTICAL values to wgt
    {
        const int ka = lane, kb = lane + 32;
        const float cosA = dots[ka] / (cn * fmaxf(sqrtf(nrm_s[ka]), EPS));
        const float cosB = (kb < KT)
            ? dots[kb] / (cn * fmaxf(sqrtf(nrm_s[kb]), EPS)) : -1e30f;
        float m = fmaxf(cosA, cosB);
        #pragma unroll
        for (int o = 16; o; o >>= 1) m = fmaxf(m, __shfl_xor_sync(0xFFFFFFFFu, m, o));
        const float eA = __expf(cosA - m);
        const float eB = (kb < KT) ? __expf(cosB - m) : 0.f;
        const float inv = 1.f / wred_sum(eA + eB);
        wgt[ka] = eA * inv;
        if (kb < KT) wgt[kb] = eB * inv;
    }
    __syncwarp();   // each warp wrote all KT entries itself

    // --- weighted sum: float4 weight chunks (1 broadcast wf per 4 rows) ---
    const float* wg = wgt;
    float ax = 0.f, ay = 0.f, bx = 0.f, by = 0.f;
    #pragma unroll
    for (int k4 = 0; k4 < K1; k4 += 4) {
        const float4 wq = *((const float4*)(wg + k4));
        const float2 va = __half22float2(((const __half2*)(nb_h + (k4 + 0) * H))[tid]);
        ax = fmaf(wq.x, va.x, ax); ay = fmaf(wq.x, va.y, ay);
        const float2 vb = __half22float2(((const __half2*)(nb_h + (k4 + 1) * H))[tid]);
        ax = fmaf(wq.y, vb.x, ax); ay = fmaf(wq.y, vb.y, ay);
        const float2 vc = __half22float2(((const __half2*)(nb_h + (k4 + 2) * H))[tid]);
        ax = fmaf(wq.z, vc.x, ax); ay = fmaf(wq.z, vc.y, ay);
        const float2 vd = __half22float2(((const __half2*)(nb_h + (k4 + 3) * H))[tid]);
        ax = fmaf(wq.w, vd.x, ax); ay = fmaf(wq.w, vd.y, ay);
    }
    #pragma unroll
    for (int k4 = K1; k4 < KT; k4 += 4) {
        const float4 wq = *((const float4*)(wg + k4));
        const float2 va = __half22float2(((const __half2*)(nb_h + (k4 + 0) * H))[tid]);
        bx = fmaf(wq.x, va.x, bx); by = fmaf(wq.x, va.y, by);
        const float2 vb = __half22float2(((const __half2*)(nb_h + (k4 + 1) * H))[tid]);
        bx = fmaf(wq.y, vb.x, bx); by = fmaf(wq.y, vb.y, by);
        const float2 vc = __half22float2(((const __half2*)(nb_h + (k4 + 2) * H))[tid]);
        bx = fmaf(wq.z, vc.x, bx); by = fmaf(wq.z, vc.y, by);
        const float2 vd = __half22float2(((const __half2*)(nb_h + (k4 + 3) * H))[tid]);
        bx = fmaf(wq.w, vd.x, bx); by = fmaf(wq.w, vd.y, by);
    }
    const float2 wa = ((const float2*)wnb)[tid];
    const float2 wb = ((const float2*)wnb2)[tid];
    const float rx = ax * wa.x + bx * wb.x + cv.x;
    const float ry = ay * wa.y + by * wb.y + cv.y;

    ((__half2*)g_rr)[(size_t)b * (H / 2) + tid] =
        __float22half2_rn(make_float2(rx, ry));

    float* csr = g_csum_r[b & (NREP - 1)];
    atomicAdd((float2*)&csr[lbl * H + 2 * tid], make_float2(rx, ry));
    if (tid == 0) atomicAdd(&g_ccnt_r[b & (NREP - 1)][lbl], 1.f);
}

// ---------------------------------------------------------------------------
// Kernel 2r: fold replicas -> per-class mean -> norm -> g_avh = fp16(ave/an).
// ---------------------------------------------------------------------------
__global__ void k2r() {
    __shared__ float red[8];
    const int cc   = blockIdx.x;
    const int t    = threadIdx.x;
    const int lane = t & 31;
    const int warp = t >> 5;

    float s = 0.f;
    #pragma unroll
    for (int r = 0; r < NREP; r++) s += g_csum_r[r][cc * H + t];
    float cnt = 0.f;
    #pragma unroll
    for (int r = 0; r < NREP; r++) cnt += g_ccnt_r[r][cc];
    const float mean = s / fmaxf(cnt, 1.f);

    float sq = wred_sum(mean * mean);
    if (lane == 0) red[warp] = sq;
    __syncthreads();
    float an = 0.f;
    #pragma unroll
    for (int i = 0; i < 8; i++) an += red[i];
    an = fmaxf(sqrtf(an), EPS);

    g_avh[cc * H + t] = __float2half(mean / an);
}

// ---------------------------------------------------------------------------
// Kernel 3: output. 1750 CTAs x 256 threads; ONE WARP PER ROW.
// ---------------------------------------------------------------------------
__global__ void __launch_bounds__(256)
k3(float* __restrict__ out, int B) {
    __shared__ __align__(16) __half avh_s[NB_CLASSES * H];
    const int tid  = threadIdx.x;
    const int lane = tid & 31;
    const int warp = tid >> 5;

    for (int i = tid; i < NB_CLASSES * H / 8; i += 256)
        ((uint4*)avh_s)[i] = ((const uint4*)g_avh)[i];
    __syncthreads();

    const int b = blockIdx.x * 8 + warp;
    if (b >= B) return;

    union { uint4 u; __half2 h[4]; } pk;
    pk.u = ((const uint4*)(g_rr + (size_t)b * H))[lane];
    const float2 v0 = __half22float2(pk.h[0]);
    const float2 v1 = __half22float2(pk.h[1]);
    const float2 v2 = __half22float2(pk.h[2]);
    const float2 v3 = __half22float2(pk.h[3]);

    float d[NB_CLASSES];
    #pragma unroll
    for (int cc = 0; cc < NB_CLASSES; cc++) {
        union { uint4 u; __half2 h[4]; } av;
        av.u = ((const uint4*)(avh_s + cc * H))[lane];
        const float2 a0 = __half22float2(av.h[0]);
        const float2 a1 = __half22float2(av.h[1]);
        const float2 a2 = __half22float2(av.h[2]);
        const float2 a3 = __half22float2(av.h[3]);
        d[cc] = v0.x * a0.x + v0.y * a0.y + v1.x * a1.x + v1.y * a1.y
              + v2.x * a2.x + v2.y * a2.y + v3.x * a3.x + v3.y * a3.y;
    }
    float rsq = v0.x * v0.x + v0.y * v0.y + v1.x * v1.x + v1.y * v1.y
              + v2.x * v2.x + v2.y * v2.y + v3.x * v3.x + v3.y * v3.y;

    #pragma unroll
    for (int o = 16; o; o >>= 1) {
        #pragma unroll
        for (int cc = 0; cc < NB_CLASSES; cc++)
            d[cc] += __shfl_xor_sync(0xFFFFFFFFu, d[cc], o);
        rsq += __shfl_xor_sync(0xFFFFFFFFu, rsq, o);
    }
    const float inv_rbn = 1.f / fmaxf(sqrtf(rsq), EPS);

    float m = -1e30f;
    #pragma unroll
    for (int cc = 0; cc < NB_CLASSES; cc++) {
        d[cc] *= inv_rbn;
        m = fmaxf(m, d[cc]);
    }
    float s = 0.f;
    #pragma unroll
    for (int cc = 0; cc < NB_CLASSES; cc++) {
        d[cc] = __expf(d[cc] - m);
        s += d[cc];
    }
    const float inv = 1.f / s;
    if (lane < NB_CLASSES) {
        float v = 0.f;
        #pragma unroll
        for (int cc = 0; cc < NB_CLASSES; cc++)
            if (lane == cc) v = d[cc] * inv;
        out[b * NB_CLASSES + lane] = v;
    }
}

// ---------------------------------------------------------------------------
// Generic fallback (any K1/K2), fp32 path -> replica 0
// ---------------------------------------------------------------------------
__global__ void kzf() {
    const int i = blockIdx.x * blockDim.x + threadIdx.x;
    if (i < NB_CLASSES * H) {
        #pragma unroll
        for (int r = 0; r < NREP; r++) g_csum_r[r][i] = 0.f;
    }
    if (i < NB_CLASSES) {
        #pragma unroll
        for (int r = 0; r < NREP; r++) g_ccnt_r[r][i] = 0.f;
    }
}

__global__ void k1g(const float* __restrict__ embeds,
                    const float* __restrict__ wself,
                    const float* __restrict__ wnb,
                    const float* __restrict__ wnb2,
                    const int* __restrict__ idx,
                    const int* __restrict__ labels,
                    const int* __restrict__ nbr,
                    const int* __restrict__ nbr2,
                    int K1, int K2) {
    extern __shared__ float sh[];
    const int KT = K1 + K2;
    float* nb_s = sh;
    float* cen  = sh + KT * H;
    float* dots = cen + H;
    float* nrms = dots + KT;
    float* wgt  = nrms + KT;
    float* red  = wgt + KT;

    const int b    = blockIdx.x;
    const int tid  = threadIdx.x;
    const int lane = tid & 31;
    const int warp = tid >> 5;

    const int crow = idx[b];
    const float c = embeds[(size_t)crow * H + tid] * wself[tid];
    cen[tid] = c;
    float cs = wred_sum(c * c);
    if (lane == 0) red[warp] = cs;
    __syncthreads();

    float cn = 0.f;
    #pragma unroll
    for (int i = 0; i < 8; i++) cn += red[i];
    cn = fmaxf(sqrtf(cn), EPS);

    const float4* cen4 = (const float4*)cen;
    const float4 c0 = cen4[lane];
    const float4 c1 = cen4[lane + 32];

    for (int k = warp; k < KT; k += 8) {
        const int r = (k < K1) ? nbr[b * K1 + k] : nbr2[b * K2 + (k - K1)];
        const float4* src = (const float4*)(embeds + (size_t)r * H);
        const float4* wv  = (const float4*)((k < K1) ? wnb : wnb2);
        float4 e0 = src[lane];
        float4 e1 = src[lane + 32];
        const float4 w0 = wv[lane];
        const float4 w1 = wv[lane + 32];
        e0.x *= w0.x; e0.y *= w0.y; e0.z *= w0.z; e0.w *= w0.w;
        e1.x *= w1.x; e1.y *= w1.y; e1.z *= w1.z; e1.w *= w1.w;

        float d = e0.x * c0.x + e0.y * c0.y + e0.z * c0.z + e0.w * c0.w
                + e1.x * c1.x + e1.y * c1.y + e1.z * c1.z + e1.w * c1.w;
        float s = e0.x * e0.x + e0.y * e0.y + e0.z * e0.z + e0.w * e0.w
                + e1.x * e1.x + e1.y * e1.y + e1.z * e1.z + e1.w * e1.w;

        float4* dst = (float4*)(nb_s + k * H);
        dst[lane]      = e0;
        dst[lane + 32] = e1;

        d = wred_sum(d);
        s = wred_sum(s);
        if (lane == 0) { dots[k] = d; nrms[k] = s; }
    }
    __syncthreads();

    if (warp == 0) {
        const int ka = lane, kb = lane + 32;
        float cosA = -1e30f, cosB = -1e30f;
        if (ka < KT) cosA = dots[ka] / (cn * fmaxf(sqrtf(nrms[ka]), EPS));
        if (kb < KT) cosB = dots[kb] / (cn * fmaxf(sqrtf(nrms[kb]), EPS));
        float m = fmaxf(cosA, cosB);
        #pragma unroll
        for (int o = 16; o; o >>= 1) m = fmaxf(m, __shfl_xor_sync(0xFFFFFFFFu, m, o));
        float eA = (ka < KT) ? __expf(cosA - m) : 0.f;
        float eB = (kb < KT) ? __expf(cosB - m) : 0.f;
        const float inv = 1.f / wred_sum(eA + eB);
        if (ka < KT) wgt[ka] = eA * inv;
        if (kb < KT) wgt[kb] = eB * inv;
    }
    __syncthreads();

    float acc = 0.f;
    for (int k = 0; k < KT; k++)
        acc = fmaf(wgt[k], nb_s[k * H + tid], acc);
    const float rr = acc + c;

    g_rr[(size_t)b * H + tid] = __float2half(rr);

    const int lbl = labels[b];
    atomicAdd(&g_csum_r[0][lbl * H + tid], rr);
    if (tid == 0) atomicAdd(&g_ccnt_r[0][lbl], 1.f);
}

// ---------------------------------------------------------------------------
extern "C" void kernel_launch(void* const* d_in, const int* in_sizes, int n_in,
                              void* d_out, int out_size) {
    const float* embeds = (const float*)d_in[0];
    const float* wself  = (const float*)d_in[1];
    const float* wnb    = (const float*)d_in[2];
    const float* wnb2   = (const float*)d_in[3];
    const int*   idx    = (const int*)d_in[4];
    const int*   labels = (const int*)d_in[5];
    const int*   nbr    = (const int*)d_in[6];
    const int*   nbr2   = (const int*)d_in[7];
    float* out = (float*)d_out;

    const int B  = in_sizes[4];
    const int K1 = in_sizes[6] / B;
    const int K2 = in_sizes[7] / B;
    const int KT = K1 + K2;
    const int N  = in_sizes[0] / H;

    if (K1 == 16 && K2 == 32 && N <= N_MAX && B <= B_MAX) {
        kc<<<2048, 256>>>(embeds, wnb, wnb2, N);
        k1s<16, 32><<<B, 128>>>(wself, wnb, wnb2, idx, labels, nbr, nbr2);
    } else {
        const size_t smem = (size_t)(KT * H + H + 3 * KT + 32) * sizeof(float);
        cudaFuncSetAttribute(k1g, cudaFuncAttributeMaxDynamicSharedMemorySize, (int)smem);
        kzf<<<NB_CLASSES, 256>>>();
        k1g<<<B, 256, smem>>>(embeds, wself, wnb, wnb2, idx, labels, nbr, nbr2, K1, K2);
    }
    k2r<<<NB_CLASSES, 256>>>();
    k3<<<(B + 7) / 8, 256>>>(out, B);
}